// round 2
// baseline (speedup 1.0000x reference)
#include <cuda_runtime.h>
#include <math.h>

typedef unsigned long long u64;
typedef unsigned int u32;

#define FSZ 50
#define NPOS 2500          // 50*50
#define KTOT 4608          // 512*9
#define NPAD 2560          // padded N for GEMM (40 tiles of 64)
#define NANCH 22500        // 2500*9
#define SORT_N 32768
#define PRE_NMS 6000
#define NWORDS 94          // ceil(6000/64)
#define POST_NMS 300

// ---------------- scratch (__device__ globals; no runtime allocation) ----------------
__device__ float g_im2col[(size_t)KTOT * NPAD];          // 47.2 MB, [k][n]
__device__ float g_featT[(size_t)NPOS * 512];            // 5.1 MB, [n][m] (transposed)
__device__ float g_boxes[NANCH * 4];
__device__ u64   g_keys[SORT_N];
__device__ float g_sx1[PRE_NMS], g_sy1[PRE_NMS], g_sx2[PRE_NMS], g_sy2[PRE_NMS], g_sarea[PRE_NMS];
__device__ u64   g_mask[(size_t)PRE_NMS * NWORDS];       // 4.5 MB

// ---------------- im2col (batch 7 only) ----------------
__global__ void im2col_k(const float* __restrict__ x) {
    size_t idx = (size_t)blockIdx.x * 256 + threadIdx.x;
    if (idx >= (size_t)KTOT * NPAD) return;
    int k = (int)(idx / NPAD);
    int p = (int)(idx - (size_t)k * NPAD);
    float v = 0.f;
    if (p < NPOS) {
        int i  = k / 9;
        int r  = k - i * 9;
        int ky = r / 3;
        int kx = r - ky * 3;
        int y  = p / FSZ;
        int xw = p - y * FSZ;
        int yy = y + ky - 1;
        int xx = xw + kx - 1;
        if (yy >= 0 && yy < FSZ && xx >= 0 && xx < FSZ)
            v = x[(size_t)i * NPOS + yy * FSZ + xx];
    }
    g_im2col[idx] = v;
}

// ---------------- fp32 GEMM conv: feat[m][n] = sum_k W[m][k]*im2col[k][n], bias+leaky,
// stored transposed into g_featT[n][m] ----------------
__global__ __launch_bounds__(256) void conv_gemm_k(const float* __restrict__ W,
                                                   const float* __restrict__ bias) {
    __shared__ float As[16][68];   // [k][m]
    __shared__ float Bs[16][68];   // [k][n]
    int t  = threadIdx.x;
    int m0 = blockIdx.y * 64;
    int n0 = blockIdx.x * 64;
    int arow = t >> 2, aseg = t & 3;    // A: 64 m-rows, 4 k-floats each
    int brow = t >> 4, bseg = t & 15;   // B: 16 k-rows, 16 n-float4s each
    const float* aG = W + (size_t)(m0 + arow) * KTOT + aseg * 4;
    const float* bG = g_im2col + (size_t)brow * NPAD + n0 + bseg * 4;

    float4 ar = *(const float4*)aG;
    float4 br = *(const float4*)bG;

    float acc[4][4];
#pragma unroll
    for (int i = 0; i < 4; ++i)
#pragma unroll
        for (int j = 0; j < 4; ++j) acc[i][j] = 0.f;

    int ty = t >> 4, tx = t & 15;

    const int ITERS = KTOT / 16;   // 288
    for (int it = 0; it < ITERS; ++it) {
        As[aseg * 4 + 0][arow] = ar.x;
        As[aseg * 4 + 1][arow] = ar.y;
        As[aseg * 4 + 2][arow] = ar.z;
        As[aseg * 4 + 3][arow] = ar.w;
        *(float4*)&Bs[brow][bseg * 4] = br;
        __syncthreads();

        if (it + 1 < ITERS) {
            ar = *(const float4*)(aG + (it + 1) * 16);
            br = *(const float4*)(bG + (size_t)(it + 1) * 16 * NPAD);
        }

#pragma unroll
        for (int kk = 0; kk < 16; ++kk) {
            float4 a4 = *(const float4*)(&As[kk][ty << 2]);
            float4 b4 = *(const float4*)(&Bs[kk][tx << 2]);
            float av[4] = {a4.x, a4.y, a4.z, a4.w};
            float bv[4] = {b4.x, b4.y, b4.z, b4.w};
#pragma unroll
            for (int mi = 0; mi < 4; ++mi)
#pragma unroll
                for (int ni = 0; ni < 4; ++ni)
                    acc[mi][ni] = fmaf(av[mi], bv[ni], acc[mi][ni]);
        }
        __syncthreads();
    }

    float4 b4 = *(const float4*)(bias + m0 + (ty << 2));
    float bv[4] = {b4.x, b4.y, b4.z, b4.w};
#pragma unroll
    for (int ni = 0; ni < 4; ++ni) {
        int n = n0 + (tx << 2) + ni;
        if (n < NPOS) {
            float4 o;
            float v0 = acc[0][ni] + bv[0]; o.x = (v0 >= 0.f) ? v0 : 0.01f * v0;
            float v1 = acc[1][ni] + bv[1]; o.y = (v1 >= 0.f) ? v1 : 0.01f * v1;
            float v2 = acc[2][ni] + bv[2]; o.z = (v2 >= 0.f) ? v2 : 0.01f * v2;
            float v3 = acc[3][ni] + bv[3]; o.w = (v3 >= 0.f) ? v3 : 0.01f * v3;
            *(float4*)(g_featT + (size_t)n * 512 + m0 + (ty << 2)) = o;
        }
    }
}

// ---------------- heads: 1x1 convs + softmax + box decode + sort keys ----------------
__global__ void heads_k(const float* __restrict__ reg_w, const float* __restrict__ reg_b,
                        const float* __restrict__ cls_w, const float* __restrict__ cls_b) {
    int p = blockIdx.x;
    int t = threadIdx.x;
    if (p >= NPOS) {   // padding keys for sort
        int idx = NANCH + (p - NPOS) * 64 + t;
        if (idx < SORT_N) g_keys[idx] = ~0ull;
        return;
    }
    __shared__ float fcol[512];
    __shared__ float ho[54];
    // coalesced: g_featT[p][*]
    {
        const float4* src = (const float4*)(g_featT + (size_t)p * 512);
        float4* dst = (float4*)fcol;
        dst[t] = src[t];
        dst[t + 64] = src[t + 64];
    }
    __syncthreads();

    if (t < 54) {
        const float* wr = (t < 36) ? (reg_w + t * 512) : (cls_w + (t - 36) * 512);
        float bsv = (t < 36) ? reg_b[t] : cls_b[t - 36];
        float s0 = 0.f, s1 = 0.f, s2 = 0.f, s3 = 0.f;
#pragma unroll 4
        for (int k = 0; k < 512; k += 4) {
            float4 w4 = *(const float4*)(wr + k);
            s0 = fmaf(w4.x, fcol[k + 0], s0);
            s1 = fmaf(w4.y, fcol[k + 1], s1);
            s2 = fmaf(w4.z, fcol[k + 2], s2);
            s3 = fmaf(w4.w, fcol[k + 3], s3);
        }
        ho[t] = bsv + ((s0 + s1) + (s2 + s3));
    }
    __syncthreads();

    if (t < 9) {
        int a = t;
        int r = a / 3, s = a % 3;
        float ssv = 16.0f * ((s == 0) ? 8.f : (s == 1) ? 16.f : 32.f);
        float rsv = (r == 0) ? 0.5f : (r == 1) ? 1.f : 2.f;
        float ha = ssv * sqrtf(rsv);
        float wa = ssv * sqrtf(1.0f / rsv);
        int irow = p / FSZ, jcol = p - irow * FSZ;
        float cx = 16.f * (float)irow + 8.f;   // repeat -> first index
        float cy = 16.f * (float)jcol + 8.f;   // tile   -> second index
        float x1a = cx - wa * 0.5f;
        float y1a = cy - ha * 0.5f;

        float pr0 = ho[a * 4 + 0], pr1 = ho[a * 4 + 1], pr2 = ho[a * 4 + 2], pr3 = ho[a * 4 + 3];
        float c0 = ho[36 + a * 2 + 0], c1 = ho[36 + a * 2 + 1];
        float mx = fmaxf(c0, c1);
        float e0 = expf(c0 - mx), e1 = expf(c1 - mx);
        float sc = e1 / (e0 + e1);

        const float hi = 799.f;
        float t0 = pr0 + x1a, t1 = pr1 + y1a;
        float rx1 = fminf(fmaxf(t0, 0.f), hi);
        float ry1 = fminf(fmaxf(t1, 0.f), hi);
        float rx2 = fminf(fmaxf((t0 + pr2) + wa, 0.f), hi);
        float ry2 = fminf(fmaxf((t1 + pr3) + ha, 0.f), hi);
        float wv = pr2 + wa, hv = pr3 + ha;
        bool valid = (wv >= 16.f) && (hv >= 16.f);
        float skey = valid ? sc : -INFINITY;

        int n = p * 9 + a;
        g_boxes[n * 4 + 0] = rx1;
        g_boxes[n * 4 + 1] = ry1;
        g_boxes[n * 4 + 2] = rx2;
        g_boxes[n * 4 + 3] = ry2;

        u32 b = __float_as_uint(skey);
        b = (b & 0x80000000u) ? ~b : (b | 0x80000000u);   // orderable (ascending)
        g_keys[n] = ((u64)(~b) << 32) | (u64)(u32)n;      // asc u64 == desc score, asc idx
    }
}

// ---------------- bitonic sort (ascending) of g_keys[32768] ----------------
__global__ __launch_bounds__(1024) void sort_p1() {
    __shared__ u64 s[2048];
    int t = threadIdx.x;
    int base = blockIdx.x * 2048;
    s[t] = g_keys[base + t];
    s[t + 1024] = g_keys[base + t + 1024];
    __syncthreads();
    for (int k = 2; k <= 2048; k <<= 1) {
        for (int j = k >> 1; j > 0; j >>= 1) {
            int li = ((t & ~(j - 1)) << 1) | (t & (j - 1));
            int pr = li | j;
            bool up = (((base + li) & k) == 0);
            u64 a = s[li], b = s[pr];
            if ((a > b) == up) { s[li] = b; s[pr] = a; }
            __syncthreads();
        }
    }
    g_keys[base + t] = s[t];
    g_keys[base + t + 1024] = s[t + 1024];
}

__global__ __launch_bounds__(1024) void sort_g(int j, int k) {
    int t = blockIdx.x * 1024 + threadIdx.x;   // 16384 threads
    int i = ((t & ~(j - 1)) << 1) | (t & (j - 1));
    int pr = i | j;
    bool up = ((i & k) == 0);
    u64 a = g_keys[i], b = g_keys[pr];
    if ((a > b) == up) { g_keys[i] = b; g_keys[pr] = a; }
}

__global__ __launch_bounds__(1024) void sort_l(int k) {
    __shared__ u64 s[2048];
    int t = threadIdx.x;
    int base = blockIdx.x * 2048;
    s[t] = g_keys[base + t];
    s[t + 1024] = g_keys[base + t + 1024];
    __syncthreads();
    for (int j = 1024; j > 0; j >>= 1) {
        int li = ((t & ~(j - 1)) << 1) | (t & (j - 1));
        int pr = li | j;
        bool up = (((base + li) & k) == 0);
        u64 a = s[li], b = s[pr];
        if ((a > b) == up) { s[li] = b; s[pr] = a; }
        __syncthreads();
    }
    g_keys[base + t] = s[t];
    g_keys[base + t + 1024] = s[t + 1024];
}

// ---------------- gather top-6000 boxes in score order ----------------
__global__ void gather_k() {
    int r = blockIdx.x * 256 + threadIdx.x;
    if (r >= PRE_NMS) return;
    u32 n = (u32)(g_keys[r] & 0xffffffffu);
    float x1 = g_boxes[n * 4 + 0];
    float y1 = g_boxes[n * 4 + 1];
    float x2 = g_boxes[n * 4 + 2];
    float y2 = g_boxes[n * 4 + 3];
    g_sx1[r] = x1; g_sy1[r] = y1; g_sx2[r] = x2; g_sy2[r] = y2;
    g_sarea[r] = (x2 - x1 + 1.f) * (y2 - y1 + 1.f);
}

// ---------------- NMS suppression bitmask (replicates reference's yy2=max bug) ----------------
__global__ void nms_mask_k() {
    int bi = blockIdx.y, bj = blockIdx.x;
    if (bj < bi) return;   // only j > i ever consumed
    __shared__ float jx1[64], jy1[64], jx2[64], jy2[64], jar[64];
    int t = threadIdx.x;   // 64 threads
    {
        int j = bj * 64 + t;
        bool v = j < PRE_NMS;
        jx1[t] = v ? g_sx1[j] : 0.f;
        jy1[t] = v ? g_sy1[j] : 0.f;
        jx2[t] = v ? g_sx2[j] : 0.f;
        jy2[t] = v ? g_sy2[j] : 0.f;
        jar[t] = v ? g_sarea[j] : 1.f;
    }
    __syncthreads();
    int i = bi * 64 + t;
    if (i >= PRE_NMS) return;
    float x1 = g_sx1[i], y1 = g_sy1[i], x2 = g_sx2[i], y2 = g_sy2[i], ar = g_sarea[i];
    u64 bits = 0;
    int jmax = PRE_NMS - bj * 64; if (jmax > 64) jmax = 64;
#pragma unroll 4
    for (int jj = 0; jj < 64; ++jj) {
        if (jj < jmax) {
            float xx1 = fmaxf(x1, jx1[jj]);
            float yy1 = fmaxf(y1, jy1[jj]);
            float xx2 = fminf(x2, jx2[jj]);
            float yy2 = fmaxf(y2, jy2[jj]);      // reference bug: max, not min
            float w = fmaxf(0.f, xx2 - xx1 + 1.f);
            float h = fmaxf(0.f, yy2 - yy1 + 1.f);
            float inter = w * h;
            float ov = inter / (ar + jar[jj] - inter);
            if (ov > 0.7f) bits |= (1ull << jj);
        }
    }
    g_mask[(size_t)i * NWORDS + bj] = bits;
}

// ---------------- sequential NMS reduce + output (single block) ----------------
__global__ __launch_bounds__(128) void nms_reduce_k(float* __restrict__ out) {
    __shared__ u64 remv[NWORDS];
    __shared__ u64 diag[64];
    __shared__ int s_count;
    __shared__ int s_stop;
    __shared__ int sel[POST_NMS];
    int t = threadIdx.x;
    if (t < NWORDS) remv[t] = 0;
    if (t == 0) { s_count = 0; s_stop = 0; }
    __syncthreads();

    for (int c = 0; c < NWORDS; ++c) {
        int nvalid = PRE_NMS - c * 64; if (nvalid > 64) nvalid = 64;
        if (t < nvalid) diag[t] = g_mask[(size_t)(c * 64 + t) * NWORDS + c];
        __syncthreads();
        if (t == 0) {
            u64 rem = remv[c];
            for (int b = 0; b < nvalid; ++b) {
                if (!((rem >> b) & 1ull)) {
                    u64 excl = (b == 63) ? 0ull : (~0ull << (b + 1));
                    rem |= diag[b] & excl;
                }
            }
            if (nvalid < 64) rem |= (~0ull << nvalid);   // mark invalid slots suppressed
            remv[c] = rem;
            u64 vm = (nvalid == 64) ? ~0ull : ((1ull << nvalid) - 1ull);
            s_count += __popcll(~rem & vm);
            if (s_count >= POST_NMS || c == NWORDS - 1) s_stop = 1;
        }
        __syncthreads();
        if (s_stop) break;
        if (t > c && t < NWORDS) {
            u64 word = remv[t];
            u64 keepbits = ~remv[c];
            const u64* mrow = g_mask + (size_t)(c * 64) * NWORDS + t;
#pragma unroll 8
            for (int b = 0; b < 64; ++b) {
                if ((keepbits >> b) & 1ull) word |= mrow[(size_t)b * NWORDS];
            }
            remv[t] = word;
        }
        __syncthreads();
    }

    if (t == 0) {
        int cnt = 0;
        for (int c = 0; c < NWORDS && cnt < POST_NMS; ++c) {
            int nvalid = PRE_NMS - c * 64; if (nvalid > 64) nvalid = 64;
            u64 vm = (nvalid == 64) ? ~0ull : ((1ull << nvalid) - 1ull);
            u64 kept = (~remv[c]) & vm;
            while (kept && cnt < POST_NMS) {
                int b = __ffsll((long long)kept) - 1;
                kept &= kept - 1;
                sel[cnt++] = c * 64 + b;
            }
        }
        // fill remainder with suppressed boxes in ascending index order (reference semantics)
        for (int c = 0; c < NWORDS && cnt < POST_NMS; ++c) {
            int nvalid = PRE_NMS - c * 64; if (nvalid > 64) nvalid = 64;
            u64 vm = (nvalid == 64) ? ~0ull : ((1ull << nvalid) - 1ull);
            u64 sup = remv[c] & vm;
            while (sup && cnt < POST_NMS) {
                int b = __ffsll((long long)sup) - 1;
                sup &= sup - 1;
                sel[cnt++] = c * 64 + b;
            }
        }
    }
    __syncthreads();
    for (int r = t; r < POST_NMS; r += 128) {
        int i = sel[r];
        float x1 = g_sx1[i], y1 = g_sy1[i], x2 = g_sx2[i], y2 = g_sy2[i];
        out[r * 4 + 0] = x1;
        out[r * 4 + 1] = y1;
        out[r * 4 + 2] = x2 - x1 + 1.f;
        out[r * 4 + 3] = y2 - y1 + 1.f;
    }
}

// ---------------- launch ----------------
extern "C" void kernel_launch(void* const* d_in, const int* in_sizes, int n_in,
                              void* d_out, int out_size) {
    const float* in_features = (const float*)d_in[0];
    const float* conv_w = (const float*)d_in[1];
    const float* conv_b = (const float*)d_in[2];
    const float* reg_w  = (const float*)d_in[3];
    const float* reg_b  = (const float*)d_in[4];
    const float* cls_w  = (const float*)d_in[5];
    const float* cls_b  = (const float*)d_in[6];
    float* out = (float*)d_out;

    const float* x7 = in_features + (size_t)7 * 512 * NPOS;   // only batch -1 is consumed

    im2col_k<<<(unsigned)(((size_t)KTOT * NPAD + 255) / 256), 256>>>(x7);
    conv_gemm_k<<<dim3(NPAD / 64, 512 / 64), 256>>>(conv_w, conv_b);

    int pad_blocks = (SORT_N - NANCH + 63) / 64;   // 161
    heads_k<<<NPOS + pad_blocks, 64>>>(reg_w, reg_b, cls_w, cls_b);

    sort_p1<<<SORT_N / 2048, 1024>>>();
    for (int k = 4096; k <= SORT_N; k <<= 1) {
        for (int j = k >> 1; j >= 2048; j >>= 1)
            sort_g<<<SORT_N / 2048, 1024>>>(j, k);
        sort_l<<<SORT_N / 2048, 1024>>>(k);
    }

    gather_k<<<(PRE_NMS + 255) / 256, 256>>>();
    nms_mask_k<<<dim3(NWORDS, NWORDS), 64>>>();
    nms_reduce_k<<<1, 128>>>(out);
}

// round 3
// speedup vs baseline: 1.0520x; 1.0520x over previous
#include <cuda_runtime.h>
#include <math.h>

typedef unsigned long long u64;
typedef unsigned int u32;

#define FSZ 50
#define NPOS 2500          // 50*50
#define KTOT 4608          // 512*9
#define NPAD 2560          // padded N for GEMM
#define NANCH 22500        // 2500*9
#define SORT_N 32768
#define PRE_NMS 6000
#define NWORDS 94          // ceil(6000/64)
#define POST_NMS 300

// GEMM config
#define TM 128
#define TN 128
#define TK 16
#define SPLITK 4
#define KS (KTOT / SPLITK)       // 1152
#define GITERS (KS / TK)         // 72
#define ASTR 132                 // padded smem row stride (floats), 16B-aligned

// ---------------- scratch (__device__ globals; no runtime allocation) ----------------
__device__ float g_im2col[(size_t)KTOT * NPAD];          // 47.2 MB, [k][n]
__device__ float g_part[SPLITK][512][NPAD];              // 21 MB split-K partials
__device__ float g_featT[(size_t)NPOS * 512];            // 5.1 MB, [n][m] (transposed)
__device__ float g_boxes[NANCH * 4];
__device__ u64   g_keys[SORT_N];
__device__ float g_sx1[PRE_NMS], g_sy1[PRE_NMS], g_sx2[PRE_NMS], g_sy2[PRE_NMS], g_sarea[PRE_NMS];
__device__ u64   g_mask[(size_t)PRE_NMS * NWORDS];       // 4.5 MB

// ---------------- packed fp32 helpers ----------------
__device__ __forceinline__ u64 bcast2(float x) {
    u64 r; asm("mov.b64 %0, {%1, %1};" : "=l"(r) : "f"(x)); return r;
}
__device__ __forceinline__ void ffma2(u64& acc, u64 a, u64 b) {
    asm("fma.rn.f32x2 %0, %1, %2, %0;" : "+l"(acc) : "l"(a), "l"(b));
}
__device__ __forceinline__ void unpack2(u64 v, float& lo, float& hi) {
    asm("mov.b64 {%0, %1}, %2;" : "=f"(lo), "=f"(hi) : "l"(v));
}
#define CPA(dst, src)  asm volatile("cp.async.cg.shared.global [%0], [%1], 16;" :: "r"(dst), "l"(src))
#define CPCOMMIT()     asm volatile("cp.async.commit_group;" ::: "memory")
#define CPWAIT0()      asm volatile("cp.async.wait_group 0;" ::: "memory")

// ---------------- im2col (batch 7 only) ----------------
__global__ void im2col_k(const float* __restrict__ x) {
    size_t idx = (size_t)blockIdx.x * 256 + threadIdx.x;
    if (idx >= (size_t)KTOT * NPAD) return;
    int k = (int)(idx / NPAD);
    int p = (int)(idx - (size_t)k * NPAD);
    float v = 0.f;
    if (p < NPOS) {
        int i  = k / 9;
        int r  = k - i * 9;
        int ky = r / 3;
        int kx = r - ky * 3;
        int y  = p / FSZ;
        int xw = p - y * FSZ;
        int yy = y + ky - 1;
        int xx = xw + kx - 1;
        if (yy >= 0 && yy < FSZ && xx >= 0 && xx < FSZ)
            v = x[(size_t)i * NPOS + yy * FSZ + xx];
    }
    g_im2col[idx] = v;
}

// ---------------- packed-fp32 split-K GEMM: part[z][m][n] = sum_{k in split z} W[m][k]*B[k][n] ----
__global__ __launch_bounds__(256) void conv_gemm_k(const float* __restrict__ W) {
    __shared__ float As[2][TK][ASTR];   // [k][m]
    __shared__ float Bs[2][TK][ASTR];   // [k][n]
    int t  = threadIdx.x;
    int m0 = blockIdx.y * TM;
    int n0 = blockIdx.x * TN;
    int z  = blockIdx.z;
    int kbase = z * KS;

    int arow = t >> 1;            // 0..127 (m within tile)
    int ak   = (t & 1) * 8;       // 0 or 8 (k offset)
    int brow = t >> 4;            // 0..15  (k within step)
    int bn   = (t & 15) * 4;      // 0..60  (n offset)

    const float* aG = W + (size_t)(m0 + arow) * KTOT + kbase + ak;
    const float* bG = g_im2col + (size_t)(kbase + brow) * NPAD + n0 + bn;

    u32 bs0 = (u32)__cvta_generic_to_shared(&Bs[0][0][0]) + (u32)((brow * ASTR + bn) * 4);
    u32 bs1 = bs0 + (u32)(TK * ASTR * 4);

    // prologue: A regs + B cp.async for it=0
    float4 ar0 = *(const float4*)aG;
    float4 ar1 = *(const float4*)(aG + 4);
    CPA(bs0, bG);
    CPA(bs0 + 256, bG + 64);
    CPCOMMIT();

    u64 acc[4][8];
#pragma unroll
    for (int i = 0; i < 4; ++i)
#pragma unroll
        for (int j = 0; j < 8; ++j) acc[i][j] = 0ull;

    int ty = t >> 4, tx = t & 15;
    int tm0 = ty * 8, tn0 = tx * 8;

    for (int it = 0; it < GITERS; ++it) {
        int cur = it & 1;
        CPWAIT0();
        // store A (transposed) into current buffer
        {
            float* Ac = &As[cur][0][0];
            Ac[(ak + 0) * ASTR + arow] = ar0.x;
            Ac[(ak + 1) * ASTR + arow] = ar0.y;
            Ac[(ak + 2) * ASTR + arow] = ar0.z;
            Ac[(ak + 3) * ASTR + arow] = ar0.w;
            Ac[(ak + 4) * ASTR + arow] = ar1.x;
            Ac[(ak + 5) * ASTR + arow] = ar1.y;
            Ac[(ak + 6) * ASTR + arow] = ar1.z;
            Ac[(ak + 7) * ASTR + arow] = ar1.w;
        }
        __syncthreads();

        if (it + 1 < GITERS) {
            int nxt = cur ^ 1;
            const float* bGn = bG + (size_t)(it + 1) * TK * NPAD;
            u32 bsn = nxt ? bs1 : bs0;
            CPA(bsn, bGn);
            CPA(bsn + 256, bGn + 64);
            CPCOMMIT();
            const float* aGn = aG + (it + 1) * TK;
            ar0 = *(const float4*)aGn;
            ar1 = *(const float4*)(aGn + 4);
        }

#pragma unroll
        for (int kk = 0; kk < TK; ++kk) {
            const float* asr = &As[cur][kk][tm0];
            const float* bsr = &Bs[cur][kk][tn0];
            ulonglong2 av0 = *(const ulonglong2*)(asr);       // m pairs (0,1),(2,3)
            ulonglong2 av1 = *(const ulonglong2*)(asr + 4);   // m pairs (4,5),(6,7)
            float4 bq0 = *(const float4*)(bsr);
            float4 bq1 = *(const float4*)(bsr + 4);
            u64 bb[8];
            bb[0] = bcast2(bq0.x); bb[1] = bcast2(bq0.y);
            bb[2] = bcast2(bq0.z); bb[3] = bcast2(bq0.w);
            bb[4] = bcast2(bq1.x); bb[5] = bcast2(bq1.y);
            bb[6] = bcast2(bq1.z); bb[7] = bcast2(bq1.w);
            u64 aa[4] = {av0.x, av0.y, av1.x, av1.y};
#pragma unroll
            for (int mp = 0; mp < 4; ++mp)
#pragma unroll
                for (int nj = 0; nj < 8; ++nj)
                    ffma2(acc[mp][nj], aa[mp], bb[nj]);
        }
        __syncthreads();
    }

    // epilogue: write split partials [m][n]
    float* outp = &g_part[z][0][0];
#pragma unroll
    for (int mp = 0; mp < 4; ++mp) {
        float lo[8], hi[8];
#pragma unroll
        for (int nj = 0; nj < 8; ++nj) unpack2(acc[mp][nj], lo[nj], hi[nj]);
        size_t rA = (size_t)(m0 + tm0 + mp * 2) * NPAD + n0 + tn0;
        size_t rB = rA + NPAD;
        float4 v;
        v.x = lo[0]; v.y = lo[1]; v.z = lo[2]; v.w = lo[3]; *(float4*)(outp + rA)     = v;
        v.x = lo[4]; v.y = lo[5]; v.z = lo[6]; v.w = lo[7]; *(float4*)(outp + rA + 4) = v;
        v.x = hi[0]; v.y = hi[1]; v.z = hi[2]; v.w = hi[3]; *(float4*)(outp + rB)     = v;
        v.x = hi[4]; v.y = hi[5]; v.z = hi[6]; v.w = hi[7]; *(float4*)(outp + rB + 4) = v;
    }
}

// ---------------- reduce splits + bias + leaky + transpose to featT[n][m] ----------------
__global__ void reduce_bias_k(const float* __restrict__ bias) {
    __shared__ float s[32][33];
    int tx = threadIdx.x;       // 32
    int ty = threadIdx.y;       // 8
    int n0 = blockIdx.x * 32;
    int m0 = blockIdx.y * 32;
#pragma unroll
    for (int i = 0; i < 4; ++i) {
        int ml = ty * 4 + i;
        int m  = m0 + ml;
        int n  = n0 + tx;
        float v = g_part[0][m][n] + g_part[1][m][n] + g_part[2][m][n] + g_part[3][m][n];
        v += bias[m];
        v = (v >= 0.f) ? v : 0.01f * v;
        s[ml][tx] = v;
    }
    __syncthreads();
#pragma unroll
    for (int i = 0; i < 4; ++i) {
        int nl = ty * 4 + i;
        int n  = n0 + nl;
        if (n < NPOS) g_featT[(size_t)n * 512 + m0 + tx] = s[tx][nl];
    }
}

// ---------------- heads: 1x1 convs + softmax + box decode + sort keys ----------------
__global__ void heads_k(const float* __restrict__ reg_w, const float* __restrict__ reg_b,
                        const float* __restrict__ cls_w, const float* __restrict__ cls_b) {
    int p = blockIdx.x;
    int t = threadIdx.x;
    if (p >= NPOS) {   // padding keys for sort
        int idx = NANCH + (p - NPOS) * 64 + t;
        if (idx < SORT_N) g_keys[idx] = ~0ull;
        return;
    }
    __shared__ float fcol[512];
    __shared__ float ho[54];
    {
        const float4* src = (const float4*)(g_featT + (size_t)p * 512);
        float4* dst = (float4*)fcol;
        dst[t] = src[t];
        dst[t + 64] = src[t + 64];
    }
    __syncthreads();

    if (t < 54) {
        const float* wr = (t < 36) ? (reg_w + t * 512) : (cls_w + (t - 36) * 512);
        float bsv = (t < 36) ? reg_b[t] : cls_b[t - 36];
        float s0 = 0.f, s1 = 0.f, s2 = 0.f, s3 = 0.f;
#pragma unroll 4
        for (int k = 0; k < 512; k += 4) {
            float4 w4 = *(const float4*)(wr + k);
            s0 = fmaf(w4.x, fcol[k + 0], s0);
            s1 = fmaf(w4.y, fcol[k + 1], s1);
            s2 = fmaf(w4.z, fcol[k + 2], s2);
            s3 = fmaf(w4.w, fcol[k + 3], s3);
        }
        ho[t] = bsv + ((s0 + s1) + (s2 + s3));
    }
    __syncthreads();

    if (t < 9) {
        int a = t;
        int r = a / 3, s = a % 3;
        float ssv = 16.0f * ((s == 0) ? 8.f : (s == 1) ? 16.f : 32.f);
        float rsv = (r == 0) ? 0.5f : (r == 1) ? 1.f : 2.f;
        float ha = ssv * sqrtf(rsv);
        float wa = ssv * sqrtf(1.0f / rsv);
        int irow = p / FSZ, jcol = p - irow * FSZ;
        float cx = 16.f * (float)irow + 8.f;
        float cy = 16.f * (float)jcol + 8.f;
        float x1a = cx - wa * 0.5f;
        float y1a = cy - ha * 0.5f;

        float pr0 = ho[a * 4 + 0], pr1 = ho[a * 4 + 1], pr2 = ho[a * 4 + 2], pr3 = ho[a * 4 + 3];
        float c0 = ho[36 + a * 2 + 0], c1 = ho[36 + a * 2 + 1];
        float mx = fmaxf(c0, c1);
        float e0 = expf(c0 - mx), e1 = expf(c1 - mx);
        float sc = e1 / (e0 + e1);

        const float hi = 799.f;
        float t0 = pr0 + x1a, t1 = pr1 + y1a;
        float rx1 = fminf(fmaxf(t0, 0.f), hi);
        float ry1 = fminf(fmaxf(t1, 0.f), hi);
        float rx2 = fminf(fmaxf((t0 + pr2) + wa, 0.f), hi);
        float ry2 = fminf(fmaxf((t1 + pr3) + ha, 0.f), hi);
        float wv = pr2 + wa, hv = pr3 + ha;
        bool valid = (wv >= 16.f) && (hv >= 16.f);
        float skey = valid ? sc : -INFINITY;

        int n = p * 9 + a;
        g_boxes[n * 4 + 0] = rx1;
        g_boxes[n * 4 + 1] = ry1;
        g_boxes[n * 4 + 2] = rx2;
        g_boxes[n * 4 + 3] = ry2;

        u32 b = __float_as_uint(skey);
        b = (b & 0x80000000u) ? ~b : (b | 0x80000000u);
        g_keys[n] = ((u64)(~b) << 32) | (u64)(u32)n;
    }
}

// ---------------- bitonic sort (ascending) of g_keys[32768] ----------------
__global__ __launch_bounds__(1024) void sort_p1() {
    __shared__ u64 s[2048];
    int t = threadIdx.x;
    int base = blockIdx.x * 2048;
    s[t] = g_keys[base + t];
    s[t + 1024] = g_keys[base + t + 1024];
    __syncthreads();
    for (int k = 2; k <= 2048; k <<= 1) {
        for (int j = k >> 1; j > 0; j >>= 1) {
            int li = ((t & ~(j - 1)) << 1) | (t & (j - 1));
            int pr = li | j;
            bool up = (((base + li) & k) == 0);
            u64 a = s[li], b = s[pr];
            if ((a > b) == up) { s[li] = b; s[pr] = a; }
            __syncthreads();
        }
    }
    g_keys[base + t] = s[t];
    g_keys[base + t + 1024] = s[t + 1024];
}

__global__ __launch_bounds__(1024) void sort_g(int j, int k) {
    int t = blockIdx.x * 1024 + threadIdx.x;
    int i = ((t & ~(j - 1)) << 1) | (t & (j - 1));
    int pr = i | j;
    bool up = ((i & k) == 0);
    u64 a = g_keys[i], b = g_keys[pr];
    if ((a > b) == up) { g_keys[i] = b; g_keys[pr] = a; }
}

__global__ __launch_bounds__(1024) void sort_l(int k) {
    __shared__ u64 s[2048];
    int t = threadIdx.x;
    int base = blockIdx.x * 2048;
    s[t] = g_keys[base + t];
    s[t + 1024] = g_keys[base + t + 1024];
    __syncthreads();
    for (int j = 1024; j > 0; j >>= 1) {
        int li = ((t & ~(j - 1)) << 1) | (t & (j - 1));
        int pr = li | j;
        bool up = (((base + li) & k) == 0);
        u64 a = s[li], b = s[pr];
        if ((a > b) == up) { s[li] = b; s[pr] = a; }
        __syncthreads();
    }
    g_keys[base + t] = s[t];
    g_keys[base + t + 1024] = s[t + 1024];
}

// ---------------- gather top-6000 boxes in score order ----------------
__global__ void gather_k() {
    int r = blockIdx.x * 256 + threadIdx.x;
    if (r >= PRE_NMS) return;
    u32 n = (u32)(g_keys[r] & 0xffffffffu);
    float x1 = g_boxes[n * 4 + 0];
    float y1 = g_boxes[n * 4 + 1];
    float x2 = g_boxes[n * 4 + 2];
    float y2 = g_boxes[n * 4 + 3];
    g_sx1[r] = x1; g_sy1[r] = y1; g_sx2[r] = x2; g_sy2[r] = y2;
    g_sarea[r] = (x2 - x1 + 1.f) * (y2 - y1 + 1.f);
}

// ---------------- NMS suppression bitmask (replicates reference's yy2=max bug) ----------------
__global__ void nms_mask_k() {
    int bi = blockIdx.y, bj = blockIdx.x;
    if (bj < bi) return;
    __shared__ float jx1[64], jy1[64], jx2[64], jy2[64], jar[64];
    int t = threadIdx.x;
    {
        int j = bj * 64 + t;
        bool v = j < PRE_NMS;
        jx1[t] = v ? g_sx1[j] : 0.f;
        jy1[t] = v ? g_sy1[j] : 0.f;
        jx2[t] = v ? g_sx2[j] : 0.f;
        jy2[t] = v ? g_sy2[j] : 0.f;
        jar[t] = v ? g_sarea[j] : 1.f;
    }
    __syncthreads();
    int i = bi * 64 + t;
    if (i >= PRE_NMS) return;
    float x1 = g_sx1[i], y1 = g_sy1[i], x2 = g_sx2[i], y2 = g_sy2[i], ar = g_sarea[i];
    u64 bits = 0;
    int jmax = PRE_NMS - bj * 64; if (jmax > 64) jmax = 64;
#pragma unroll 4
    for (int jj = 0; jj < 64; ++jj) {
        if (jj < jmax) {
            float xx1 = fmaxf(x1, jx1[jj]);
            float yy1 = fmaxf(y1, jy1[jj]);
            float xx2 = fminf(x2, jx2[jj]);
            float yy2 = fmaxf(y2, jy2[jj]);      // reference bug: max, not min
            float w = fmaxf(0.f, xx2 - xx1 + 1.f);
            float h = fmaxf(0.f, yy2 - yy1 + 1.f);
            float inter = w * h;
            float ov = inter / (ar + jar[jj] - inter);
            if (ov > 0.7f) bits |= (1ull << jj);
        }
    }
    g_mask[(size_t)i * NWORDS + bj] = bits;
}

// ---------------- sequential NMS reduce + output (single block) ----------------
__global__ __launch_bounds__(128) void nms_reduce_k(float* __restrict__ out) {
    __shared__ u64 remv[NWORDS];
    __shared__ u64 diag[64];
    __shared__ int s_count;
    __shared__ int s_stop;
    __shared__ int sel[POST_NMS];
    int t = threadIdx.x;
    if (t < NWORDS) remv[t] = 0;
    if (t == 0) { s_count = 0; s_stop = 0; }
    __syncthreads();

    for (int c = 0; c < NWORDS; ++c) {
        int nvalid = PRE_NMS - c * 64; if (nvalid > 64) nvalid = 64;
        if (t < nvalid) diag[t] = g_mask[(size_t)(c * 64 + t) * NWORDS + c];
        __syncthreads();
        if (t == 0) {
            u64 rem = remv[c];
            for (int b = 0; b < nvalid; ++b) {
                if (!((rem >> b) & 1ull)) {
                    u64 excl = (b == 63) ? 0ull : (~0ull << (b + 1));
                    rem |= diag[b] & excl;
                }
            }
            if (nvalid < 64) rem |= (~0ull << nvalid);
            remv[c] = rem;
            u64 vm = (nvalid == 64) ? ~0ull : ((1ull << nvalid) - 1ull);
            s_count += __popcll(~rem & vm);
            if (s_count >= POST_NMS || c == NWORDS - 1) s_stop = 1;
        }
        __syncthreads();
        if (s_stop) break;
        if (t > c && t < NWORDS) {
            u64 word = remv[t];
            u64 keepbits = ~remv[c];
            const u64* mrow = g_mask + (size_t)(c * 64) * NWORDS + t;
#pragma unroll 8
            for (int b = 0; b < 64; ++b) {
                if ((keepbits >> b) & 1ull) word |= mrow[(size_t)b * NWORDS];
            }
            remv[t] = word;
        }
        __syncthreads();
    }

    if (t == 0) {
        int cnt = 0;
        for (int c = 0; c < NWORDS && cnt < POST_NMS; ++c) {
            int nvalid = PRE_NMS - c * 64; if (nvalid > 64) nvalid = 64;
            u64 vm = (nvalid == 64) ? ~0ull : ((1ull << nvalid) - 1ull);
            u64 kept = (~remv[c]) & vm;
            while (kept && cnt < POST_NMS) {
                int b = __ffsll((long long)kept) - 1;
                kept &= kept - 1;
                sel[cnt++] = c * 64 + b;
            }
        }
        for (int c = 0; c < NWORDS && cnt < POST_NMS; ++c) {
            int nvalid = PRE_NMS - c * 64; if (nvalid > 64) nvalid = 64;
            u64 vm = (nvalid == 64) ? ~0ull : ((1ull << nvalid) - 1ull);
            u64 sup = remv[c] & vm;
            while (sup && cnt < POST_NMS) {
                int b = __ffsll((long long)sup) - 1;
                sup &= sup - 1;
                sel[cnt++] = c * 64 + b;
            }
        }
    }
    __syncthreads();
    for (int r = t; r < POST_NMS; r += 128) {
        int i = sel[r];
        float x1 = g_sx1[i], y1 = g_sy1[i], x2 = g_sx2[i], y2 = g_sy2[i];
        out[r * 4 + 0] = x1;
        out[r * 4 + 1] = y1;
        out[r * 4 + 2] = x2 - x1 + 1.f;
        out[r * 4 + 3] = y2 - y1 + 1.f;
    }
}

// ---------------- launch ----------------
extern "C" void kernel_launch(void* const* d_in, const int* in_sizes, int n_in,
                              void* d_out, int out_size) {
    const float* in_features = (const float*)d_in[0];
    const float* conv_w = (const float*)d_in[1];
    const float* conv_b = (const float*)d_in[2];
    const float* reg_w  = (const float*)d_in[3];
    const float* reg_b  = (const float*)d_in[4];
    const float* cls_w  = (const float*)d_in[5];
    const float* cls_b  = (const float*)d_in[6];
    float* out = (float*)d_out;

    const float* x7 = in_features + (size_t)7 * 512 * NPOS;   // only batch -1 is consumed

    im2col_k<<<(unsigned)(((size_t)KTOT * NPAD + 255) / 256), 256>>>(x7);
    conv_gemm_k<<<dim3(NPAD / TN, 512 / TM, SPLITK), 256>>>(conv_w);
    reduce_bias_k<<<dim3(NPAD / 32, 512 / 32), dim3(32, 8)>>>(conv_b);

    int pad_blocks = (SORT_N - NANCH + 63) / 64;   // 161
    heads_k<<<NPOS + pad_blocks, 64>>>(reg_w, reg_b, cls_w, cls_b);

    sort_p1<<<SORT_N / 2048, 1024>>>();
    for (int k = 4096; k <= SORT_N; k <<= 1) {
        for (int j = k >> 1; j >= 2048; j >>= 1)
            sort_g<<<SORT_N / 2048, 1024>>>(j, k);
        sort_l<<<SORT_N / 2048, 1024>>>(k);
    }

    gather_k<<<(PRE_NMS + 255) / 256, 256>>>();
    nms_mask_k<<<dim3(NWORDS, NWORDS), 64>>>();
    nms_reduce_k<<<1, 128>>>(out);
}

// round 6
// speedup vs baseline: 1.1374x; 1.0811x over previous
#include <cuda_runtime.h>
#include <math.h>

typedef unsigned long long u64;
typedef unsigned int u32;

#define FSZ 50
#define NPOS 2500          // 50*50
#define KTOT 4608          // 512*9
#define NPAD 2560          // padded N for GEMM
#define NANCH 22500        // 2500*9
#define SORT_N 32768
#define PRE_NMS 6000
#define NWORDS 94          // ceil(6000/64)
#define POST_NMS 300

// GEMM config
#define TM 128
#define TN 128
#define TK 16
#define SPLITK 4
#define KS (KTOT / SPLITK)       // 1152
#define GITERS (KS / TK)         // 72
#define ASTR 132                 // padded smem row stride (floats)

// ---------------- scratch (__device__ globals; no runtime allocation) ----------------
__device__ float g_im2col[(size_t)KTOT * NPAD];          // 47.2 MB, [k][n]
__device__ float g_part[SPLITK][512][NPAD];              // 21 MB split-K partials
__device__ float g_feat[(size_t)512 * NPAD];             // 5.2 MB, [m][n] channel-major
__device__ float g_head[(size_t)64 * NPAD];              // 0.66 MB, head outputs [54(64)][n]
__device__ float g_boxes[NANCH * 4];
__device__ u64   g_keys[SORT_N];
__device__ float g_sx1[PRE_NMS], g_sy1[PRE_NMS], g_sx2[PRE_NMS], g_sy2[PRE_NMS], g_sarea[PRE_NMS];
__device__ u64   g_mask[(size_t)PRE_NMS * NWORDS];       // 4.5 MB

// ---------------- packed fp32 helpers ----------------
__device__ __forceinline__ u64 bcast2(float x) {
    u64 r; asm("mov.b64 %0, {%1, %1};" : "=l"(r) : "f"(x)); return r;
}
__device__ __forceinline__ void ffma2(u64& acc, u64 a, u64 b) {
    asm("fma.rn.f32x2 %0, %1, %2, %0;" : "+l"(acc) : "l"(a), "l"(b));
}
__device__ __forceinline__ void unpack2(u64 v, float& lo, float& hi) {
    asm("mov.b64 {%0, %1}, %2;" : "=f"(lo), "=f"(hi) : "l"(v));
}
#define CPA(dst, src)  asm volatile("cp.async.cg.shared.global [%0], [%1], 16;" :: "r"(dst), "l"(src))
#define CPCOMMIT()     asm volatile("cp.async.commit_group;" ::: "memory")
#define CPWAIT0()      asm volatile("cp.async.wait_group 0;" ::: "memory")

// ---------------- im2col (batch 7 only) ----------------
__global__ void im2col_k(const float* __restrict__ x) {
    size_t idx = (size_t)blockIdx.x * 256 + threadIdx.x;
    if (idx >= (size_t)KTOT * NPAD) return;
    int k = (int)(idx / NPAD);
    int p = (int)(idx - (size_t)k * NPAD);
    float v = 0.f;
    if (p < NPOS) {
        int i  = k / 9;
        int r  = k - i * 9;
        int ky = r / 3;
        int kx = r - ky * 3;
        int y  = p / FSZ;
        int xw = p - y * FSZ;
        int yy = y + ky - 1;
        int xx = xw + kx - 1;
        if (yy >= 0 && yy < FSZ && xx >= 0 && xx < FSZ)
            v = x[(size_t)i * NPOS + yy * FSZ + xx];
    }
    g_im2col[idx] = v;
}

// ---------------- packed-fp32 split-K GEMM (bank-conflict-free compute mapping) ----------------
__global__ __launch_bounds__(256) void conv_gemm_k(const float* __restrict__ W) {
    __shared__ __align__(16) float As[2][TK][ASTR];   // [k][m]
    __shared__ __align__(16) float Bs[2][TK][ASTR];   // [k][n]
    int t  = threadIdx.x;
    int m0 = blockIdx.y * TM;
    int n0 = blockIdx.x * TN;
    int z  = blockIdx.z;
    int kbase = z * KS;

    // --- load mapping ---
    int arow = t >> 1;            // 0..127 (m within tile)
    int ak   = (t & 1) * 8;       // 0 or 8 (k offset)
    int brow = t >> 4;            // 0..15  (k within step)
    int bn   = (t & 15) * 4;      // 0..60  (n offset)

    const float* aG = W + (size_t)(m0 + arow) * KTOT + kbase + ak;
    const float* bG = g_im2col + (size_t)(kbase + brow) * NPAD + n0 + bn;

    u32 bs0 = (u32)__cvta_generic_to_shared(&Bs[0][0][0]) + (u32)((brow * ASTR + bn) * 4);
    u32 bs1 = bs0 + (u32)(TK * ASTR * 4);

    // prologue: A regs + B cp.async for it=0
    float4 ar0 = *(const float4*)aG;
    float4 ar1 = *(const float4*)(aG + 4);
    CPA(bs0, bG);
    CPA(bs0 + 256, bG + 64);
    CPCOMMIT();

    u64 acc[4][8];
#pragma unroll
    for (int i = 0; i < 4; ++i)
#pragma unroll
        for (int j = 0; j < 8; ++j) acc[i][j] = 0ull;

    // --- compute mapping (conflict-free) ---
    int warp = t >> 5, lane = t & 31;
    int mwarp = warp >> 1, nwarp = warp & 1;   // 4x2 warp grid: 32m x 64n per warp
    int lm = lane >> 3, ln = lane & 7;
    int mb = mwarp * 32 + lm * 4;              // m: mb..mb+3 and mb+16..mb+19
    int nb = nwarp * 64 + ln * 4;              // n: nb..nb+3 and nb+32..nb+35

    for (int it = 0; it < GITERS; ++it) {
        int cur = it & 1;
        CPWAIT0();
        {
            float* Ac = &As[cur][0][0];
            Ac[(ak + 0) * ASTR + arow] = ar0.x;
            Ac[(ak + 1) * ASTR + arow] = ar0.y;
            Ac[(ak + 2) * ASTR + arow] = ar0.z;
            Ac[(ak + 3) * ASTR + arow] = ar0.w;
            Ac[(ak + 4) * ASTR + arow] = ar1.x;
            Ac[(ak + 5) * ASTR + arow] = ar1.y;
            Ac[(ak + 6) * ASTR + arow] = ar1.z;
            Ac[(ak + 7) * ASTR + arow] = ar1.w;
        }
        __syncthreads();

        if (it + 1 < GITERS) {
            int nxt = cur ^ 1;
            const float* bGn = bG + (size_t)(it + 1) * TK * NPAD;
            u32 bsn = nxt ? bs1 : bs0;
            CPA(bsn, bGn);
            CPA(bsn + 256, bGn + 64);
            CPCOMMIT();
            const float* aGn = aG + (it + 1) * TK;
            ar0 = *(const float4*)aGn;
            ar1 = *(const float4*)(aGn + 4);
        }

#pragma unroll
        for (int kk = 0; kk < TK; ++kk) {
            const float* asr = &As[cur][kk][0];
            const float* bsr = &Bs[cur][kk][0];
            ulonglong2 a0 = *(const ulonglong2*)(asr + mb);        // m pairs (0,1),(2,3)
            ulonglong2 a1 = *(const ulonglong2*)(asr + mb + 16);   // m pairs (16,17),(18,19)
            float4 b0 = *(const float4*)(bsr + nb);
            float4 b1 = *(const float4*)(bsr + nb + 32);
            u64 aa[4] = {a0.x, a0.y, a1.x, a1.y};
            u64 bb[8];
            bb[0] = bcast2(b0.x); bb[1] = bcast2(b0.y);
            bb[2] = bcast2(b0.z); bb[3] = bcast2(b0.w);
            bb[4] = bcast2(b1.x); bb[5] = bcast2(b1.y);
            bb[6] = bcast2(b1.z); bb[7] = bcast2(b1.w);
#pragma unroll
            for (int mp = 0; mp < 4; ++mp)
#pragma unroll
                for (int nj = 0; nj < 8; ++nj)
                    ffma2(acc[mp][nj], aa[mp], bb[nj]);
        }
        __syncthreads();
    }

    // epilogue: write split partials [m][n]
    float* outp = &g_part[z][0][0];
#pragma unroll
    for (int mp = 0; mp < 4; ++mp) {
        float lo[8], hi[8];
#pragma unroll
        for (int nj = 0; nj < 8; ++nj) unpack2(acc[mp][nj], lo[nj], hi[nj]);
        int m = m0 + mb + ((mp & 2) << 3) + ((mp & 1) << 1);   // mp0:+0 mp1:+2 mp2:+16 mp3:+18
        size_t rA = (size_t)m * NPAD + n0 + nb;
        size_t rB = rA + NPAD;
        float4 v;
        v.x = lo[0]; v.y = lo[1]; v.z = lo[2]; v.w = lo[3]; *(float4*)(outp + rA)      = v;
        v.x = lo[4]; v.y = lo[5]; v.z = lo[6]; v.w = lo[7]; *(float4*)(outp + rA + 32) = v;
        v.x = hi[0]; v.y = hi[1]; v.z = hi[2]; v.w = hi[3]; *(float4*)(outp + rB)      = v;
        v.x = hi[4]; v.y = hi[5]; v.z = hi[6]; v.w = hi[7]; *(float4*)(outp + rB + 32) = v;
    }
}

// ---------------- reduce splits + bias + leaky -> g_feat[m][n] (channel-major) ----------------
__global__ void reduce_bias_k(const float* __restrict__ bias) {
    int idx = blockIdx.x * 256 + threadIdx.x;     // one float4 per thread
    const int N4 = NPAD / 4;
    if (idx >= 512 * N4) return;
    int m  = idx / N4;
    int n4 = idx - m * N4;
    size_t off = (size_t)m * NPAD + n4 * 4;
    float4 a = *(const float4*)(&g_part[0][0][0] + off);
    float4 b = *(const float4*)(&g_part[1][0][0] + off);
    float4 c = *(const float4*)(&g_part[2][0][0] + off);
    float4 d = *(const float4*)(&g_part[3][0][0] + off);
    float bv = bias[m];
    float4 o;
    float v;
    v = a.x + b.x + c.x + d.x + bv; o.x = (v >= 0.f) ? v : 0.01f * v;
    v = a.y + b.y + c.y + d.y + bv; o.y = (v >= 0.f) ? v : 0.01f * v;
    v = a.z + b.z + c.z + d.z + bv; o.z = (v >= 0.f) ? v : 0.01f * v;
    v = a.w + b.w + c.w + d.w + bv; o.w = (v >= 0.f) ? v : 0.01f * v;
    *(float4*)(g_feat + off) = o;
}

// ---------------- head GEMM: g_head[64][2560] = Whead[64][512] @ g_feat[512][2560] ----------------
__global__ __launch_bounds__(256) void head_gemm_k(const float* __restrict__ reg_w,
                                                   const float* __restrict__ reg_b,
                                                   const float* __restrict__ cls_w,
                                                   const float* __restrict__ cls_b) {
    __shared__ __align__(16) float As[16][68];   // [k][m] 64 m
    __shared__ __align__(16) float Bs[16][68];   // [k][n] 64 n
    int t  = threadIdx.x;
    int n0 = blockIdx.x * 64;

    int arow_h = t >> 2, akk = (t & 3) * 4;   // A: 64 rows x 16 k
    int brow = t >> 4, bnl = (t & 15) * 4;    // B: 16 k x 64 n

    // conflict-free compute mapping: 4 m-warps x 2 n-warps, 16m x 32n per warp
    int warp = t >> 5, lane = t & 31;
    int mwarp = warp >> 1, nwarp = warp & 1;
    int lm = lane >> 3, ln = lane & 7;
    int mb = mwarp * 16 + lm * 4;
    int nb = nwarp * 32 + ln * 4;

    float acc[4][4];
#pragma unroll
    for (int i = 0; i < 4; ++i)
#pragma unroll
        for (int j = 0; j < 4; ++j) acc[i][j] = 0.f;

    for (int it = 0; it < 32; ++it) {
        int k0 = it * 16;
        float4 av;
        if (arow_h < 36)       av = *(const float4*)(reg_w + arow_h * 512 + k0 + akk);
        else if (arow_h < 54)  av = *(const float4*)(cls_w + (arow_h - 36) * 512 + k0 + akk);
        else                   av = make_float4(0.f, 0.f, 0.f, 0.f);
        float4 bv = *(const float4*)(g_feat + (size_t)(k0 + brow) * NPAD + n0 + bnl);
        __syncthreads();
        As[akk + 0][arow_h] = av.x;
        As[akk + 1][arow_h] = av.y;
        As[akk + 2][arow_h] = av.z;
        As[akk + 3][arow_h] = av.w;
        *(float4*)&Bs[brow][bnl] = bv;
        __syncthreads();
#pragma unroll
        for (int kk = 0; kk < 16; ++kk) {
            float4 a4 = *(const float4*)(&As[kk][mb]);
            float4 b4 = *(const float4*)(&Bs[kk][nb]);
            float am[4] = {a4.x, a4.y, a4.z, a4.w};
            float bn2[4] = {b4.x, b4.y, b4.z, b4.w};
#pragma unroll
            for (int mi = 0; mi < 4; ++mi)
#pragma unroll
                for (int nj = 0; nj < 4; ++nj)
                    acc[mi][nj] = fmaf(am[mi], bn2[nj], acc[mi][nj]);
        }
    }

#pragma unroll
    for (int mi = 0; mi < 4; ++mi) {
        int m = mb + mi;
        float bv = 0.f;
        if (m < 36) bv = reg_b[m];
        else if (m < 54) bv = cls_b[m - 36];
        float4 o;
        o.x = acc[mi][0] + bv; o.y = acc[mi][1] + bv;
        o.z = acc[mi][2] + bv; o.w = acc[mi][3] + bv;
        *(float4*)(g_head + (size_t)m * NPAD + n0 + nb) = o;
    }
}

// ---------------- decode: softmax + box decode + sort keys (+ key padding) ----------------
__global__ void decode_k() {
    int tid = blockIdx.x * 256 + threadIdx.x;
    if (tid >= NPOS) {
        int idx = NANCH + (tid - NPOS);
        if (idx < SORT_N) g_keys[idx] = ~0ull;
        return;
    }
    int p = tid;
    float ho[54];
#pragma unroll
    for (int j = 0; j < 54; ++j) ho[j] = g_head[(size_t)j * NPAD + p];

    int irow = p / FSZ, jcol = p - irow * FSZ;
    float cx = 16.f * (float)irow + 8.f;
    float cy = 16.f * (float)jcol + 8.f;

#pragma unroll
    for (int a = 0; a < 9; ++a) {
        int r = a / 3, s = a % 3;
        float ssv = 16.0f * ((s == 0) ? 8.f : (s == 1) ? 16.f : 32.f);
        float rsv = (r == 0) ? 0.5f : (r == 1) ? 1.f : 2.f;
        float ha = ssv * sqrtf(rsv);
        float wa = ssv * sqrtf(1.0f / rsv);
        float x1a = cx - wa * 0.5f;
        float y1a = cy - ha * 0.5f;

        float pr0 = ho[a * 4 + 0], pr1 = ho[a * 4 + 1], pr2 = ho[a * 4 + 2], pr3 = ho[a * 4 + 3];
        float c0 = ho[36 + a * 2 + 0], c1 = ho[36 + a * 2 + 1];
        float mx = fmaxf(c0, c1);
        float e0 = expf(c0 - mx), e1 = expf(c1 - mx);
        float sc = e1 / (e0 + e1);

        const float hi = 799.f;
        float t0 = pr0 + x1a, t1 = pr1 + y1a;
        float rx1 = fminf(fmaxf(t0, 0.f), hi);
        float ry1 = fminf(fmaxf(t1, 0.f), hi);
        float rx2 = fminf(fmaxf((t0 + pr2) + wa, 0.f), hi);
        float ry2 = fminf(fmaxf((t1 + pr3) + ha, 0.f), hi);
        float wv = pr2 + wa, hv = pr3 + ha;
        bool valid = (wv >= 16.f) && (hv >= 16.f);
        float skey = valid ? sc : -INFINITY;

        int n = p * 9 + a;
        g_boxes[n * 4 + 0] = rx1;
        g_boxes[n * 4 + 1] = ry1;
        g_boxes[n * 4 + 2] = rx2;
        g_boxes[n * 4 + 3] = ry2;

        u32 b = __float_as_uint(skey);
        b = (b & 0x80000000u) ? ~b : (b | 0x80000000u);
        g_keys[n] = ((u64)(~b) << 32) | (u64)(u32)n;
    }
}

// ---------------- bitonic sort (ascending) of g_keys[32768] ----------------
__global__ __launch_bounds__(1024) void sort_p1() {
    __shared__ u64 s[2048];
    int t = threadIdx.x;
    int base = blockIdx.x * 2048;
    s[t] = g_keys[base + t];
    s[t + 1024] = g_keys[base + t + 1024];
    __syncthreads();
    for (int k = 2; k <= 2048; k <<= 1) {
        for (int j = k >> 1; j > 0; j >>= 1) {
            int li = ((t & ~(j - 1)) << 1) | (t & (j - 1));
            int pr = li | j;
            bool up = (((base + li) & k) == 0);
            u64 a = s[li], b = s[pr];
            if ((a > b) == up) { s[li] = b; s[pr] = a; }
            __syncthreads();
        }
    }
    g_keys[base + t] = s[t];
    g_keys[base + t + 1024] = s[t + 1024];
}

__global__ __launch_bounds__(1024) void sort_g(int j, int k) {
    int t = blockIdx.x * 1024 + threadIdx.x;
    int i = ((t & ~(j - 1)) << 1) | (t & (j - 1));
    int pr = i | j;
    bool up = ((i & k) == 0);
    u64 a = g_keys[i], b = g_keys[pr];
    if ((a > b) == up) { g_keys[i] = b; g_keys[pr] = a; }
}

__global__ __launch_bounds__(1024) void sort_l(int k) {
    __shared__ u64 s[2048];
    int t = threadIdx.x;
    int base = blockIdx.x * 2048;
    s[t] = g_keys[base + t];
    s[t + 1024] = g_keys[base + t + 1024];
    __syncthreads();
    for (int j = 1024; j > 0; j >>= 1) {
        int li = ((t & ~(j - 1)) << 1) | (t & (j - 1));
        int pr = li | j;
        bool up = (((base + li) & k) == 0);
        u64 a = s[li], b = s[pr];
        if ((a > b) == up) { s[li] = b; s[pr] = a; }
        __syncthreads();
    }
    g_keys[base + t] = s[t];
    g_keys[base + t + 1024] = s[t + 1024];
}

// ---------------- gather top-6000 boxes in score order ----------------
__global__ void gather_k() {
    int r = blockIdx.x * 256 + threadIdx.x;
    if (r >= PRE_NMS) return;
    u32 n = (u32)(g_keys[r] & 0xffffffffu);
    float x1 = g_boxes[n * 4 + 0];
    float y1 = g_boxes[n * 4 + 1];
    float x2 = g_boxes[n * 4 + 2];
    float y2 = g_boxes[n * 4 + 3];
    g_sx1[r] = x1; g_sy1[r] = y1; g_sx2[r] = x2; g_sy2[r] = y2;
    g_sarea[r] = (x2 - x1 + 1.f) * (y2 - y1 + 1.f);
}

// ---------------- NMS suppression bitmask (replicates reference's yy2=max bug) ----------------
__global__ void nms_mask_k() {
    int bi = blockIdx.y, bj = blockIdx.x;
    if (bj < bi) return;
    __shared__ float jx1[64], jy1[64], jx2[64], jy2[64], jar[64];
    int t = threadIdx.x;
    {
        int j = bj * 64 + t;
        bool v = j < PRE_NMS;
        jx1[t] = v ? g_sx1[j] : 0.f;
        jy1[t] = v ? g_sy1[j] : 0.f;
        jx2[t] = v ? g_sx2[j] : 0.f;
        jy2[t] = v ? g_sy2[j] : 0.f;
        jar[t] = v ? g_sarea[j] : 1.f;
    }
    __syncthreads();
    int i = bi * 64 + t;
    if (i >= PRE_NMS) return;
    float x1 = g_sx1[i], y1 = g_sy1[i], x2 = g_sx2[i], y2 = g_sy2[i], ar = g_sarea[i];
    u64 bits = 0;
    int jmax = PRE_NMS - bj * 64; if (jmax > 64) jmax = 64;
#pragma unroll 4
    for (int jj = 0; jj < 64; ++jj) {
        if (jj < jmax) {
            float xx1 = fmaxf(x1, jx1[jj]);
            float yy1 = fmaxf(y1, jy1[jj]);
            float xx2 = fminf(x2, jx2[jj]);
            float yy2 = fmaxf(y2, jy2[jj]);      // reference bug: max, not min
            float w = fmaxf(0.f, xx2 - xx1 + 1.f);
            float h = fmaxf(0.f, yy2 - yy1 + 1.f);
            float inter = w * h;
            float ov = inter / (ar + jar[jj] - inter);
            if (ov > 0.7f) bits |= (1ull << jj);
        }
    }
    g_mask[(size_t)i * NWORDS + bj] = bits;
}

// ---------------- sequential NMS reduce + output (single block) ----------------
__global__ __launch_bounds__(128) void nms_reduce_k(float* __restrict__ out) {
    __shared__ u64 remv[NWORDS];
    __shared__ u64 diag[64];
    __shared__ int s_count;
    __shared__ int s_stop;
    __shared__ int sel[POST_NMS];
    int t = threadIdx.x;
    if (t < NWORDS) remv[t] = 0;
    if (t == 0) { s_count = 0; s_stop = 0; }
    __syncthreads();

    for (int c = 0; c < NWORDS; ++c) {
        int nvalid = PRE_NMS - c * 64; if (nvalid > 64) nvalid = 64;
        if (t < nvalid) diag[t] = g_mask[(size_t)(c * 64 + t) * NWORDS + c];
        __syncthreads();
        if (t == 0) {
            u64 rem = remv[c];
            for (int b = 0; b < nvalid; ++b) {
                if (!((rem >> b) & 1ull)) {
                    u64 excl = (b == 63) ? 0ull : (~0ull << (b + 1));
                    rem |= diag[b] & excl;
                }
            }
            if (nvalid < 64) rem |= (~0ull << nvalid);
            remv[c] = rem;
            u64 vm = (nvalid == 64) ? ~0ull : ((1ull << nvalid) - 1ull);
            s_count += __popcll(~rem & vm);
            if (s_count >= POST_NMS || c == NWORDS - 1) s_stop = 1;
        }
        __syncthreads();
        if (s_stop) break;
        if (t > c && t < NWORDS) {
            u64 word = remv[t];
            u64 keepbits = ~remv[c];
            const u64* mrow = g_mask + (size_t)(c * 64) * NWORDS + t;
#pragma unroll 8
            for (int b = 0; b < 64; ++b) {
                if ((keepbits >> b) & 1ull) word |= mrow[(size_t)b * NWORDS];
            }
            remv[t] = word;
        }
        __syncthreads();
    }

    if (t == 0) {
        int cnt = 0;
        for (int c = 0; c < NWORDS && cnt < POST_NMS; ++c) {
            int nvalid = PRE_NMS - c * 64; if (nvalid > 64) nvalid = 64;
            u64 vm = (nvalid == 64) ? ~0ull : ((1ull << nvalid) - 1ull);
            u64 kept = (~remv[c]) & vm;
            while (kept && cnt < POST_NMS) {
                int b = __ffsll((long long)kept) - 1;
                kept &= kept - 1;
                sel[cnt++] = c * 64 + b;
            }
        }
        for (int c = 0; c < NWORDS && cnt < POST_NMS; ++c) {
            int nvalid = PRE_NMS - c * 64; if (nvalid > 64) nvalid = 64;
            u64 vm = (nvalid == 64) ? ~0ull : ((1ull << nvalid) - 1ull);
            u64 sup = remv[c] & vm;
            while (sup && cnt < POST_NMS) {
                int b = __ffsll((long long)sup) - 1;
                sup &= sup - 1;
                sel[cnt++] = c * 64 + b;
            }
        }
    }
    __syncthreads();
    for (int r = t; r < POST_NMS; r += 128) {
        int i = sel[r];
        float x1 = g_sx1[i], y1 = g_sy1[i], x2 = g_sx2[i], y2 = g_sy2[i];
        out[r * 4 + 0] = x1;
        out[r * 4 + 1] = y1;
        out[r * 4 + 2] = x2 - x1 + 1.f;
        out[r * 4 + 3] = y2 - y1 + 1.f;
    }
}

// ---------------- launch ----------------
extern "C" void kernel_launch(void* const* d_in, const int* in_sizes, int n_in,
                              void* d_out, int out_size) {
    const float* in_features = (const float*)d_in[0];
    const float* conv_w = (const float*)d_in[1];
    const float* conv_b = (const float*)d_in[2];
    const float* reg_w  = (const float*)d_in[3];
    const float* reg_b  = (const float*)d_in[4];
    const float* cls_w  = (const float*)d_in[5];
    const float* cls_b  = (const float*)d_in[6];
    float* out = (float*)d_out;

    const float* x7 = in_features + (size_t)7 * 512 * NPOS;   // only batch -1 is consumed

    im2col_k<<<(unsigned)(((size_t)KTOT * NPAD + 255) / 256), 256>>>(x7);
    conv_gemm_k<<<dim3(NPAD / TN, 512 / TM, SPLITK), 256>>>(conv_w);
    reduce_bias_k<<<(512 * (NPAD / 4) + 255) / 256, 256>>>(conv_b);

    head_gemm_k<<<NPAD / 64, 256>>>(reg_w, reg_b, cls_w, cls_b);
    decode_k<<<(NPOS + (SORT_N - NANCH) + 255) / 256, 256>>>();

    sort_p1<<<SORT_N / 2048, 1024>>>();
    for (int k = 4096; k <= SORT_N; k <<= 1) {
        for (int j = k >> 1; j >= 2048; j >>= 1)
            sort_g<<<SORT_N / 2048, 1024>>>(j, k);
        sort_l<<<SORT_N / 2048, 1024>>>(k);
    }

    gather_k<<<(PRE_NMS + 255) / 256, 256>>>();
    nms_mask_k<<<dim3(NWORDS, NWORDS), 64>>>();
    nms_reduce_k<<<1, 128>>>(out);
}